// round 4
// baseline (speedup 1.0000x reference)
#include <cuda_runtime.h>
#include <cuda_bf16.h>
#include <math.h>

#define N_NODES   100000
#define N_EDGES   1600000
#define IN_FEAT   512
#define HIDDEN    64
#define N_CLASSES 40
#define N_LAYERS  6

// ---------------- device scratch (no allocations allowed) ----------------
// Kernels reference these symbols directly from device code only.
__device__ float g_lin[N_NODES * HIDDEN];   // GEMM output (pre-propagation)
__device__ float g_agg[N_NODES * HIDDEN];   // aggregation accumulator
__device__ float g_h  [N_NODES * HIDDEN];   // layer activation
__device__ float g_jk [N_NODES * HIDDEN];   // jumping-knowledge max
__device__ float g_dinv[N_NODES];
__device__ float g_norm[N_EDGES];
__device__ int   g_deg [N_NODES];

// ---------------- degree / norm ----------------
// edge_index is INT32 in the harness (int64 inputs are lowered to int32).
__global__ void k_deg_init() {
    int i = blockIdx.x * blockDim.x + threadIdx.x;
    if (i < N_NODES) g_deg[i] = 1;   // self loop
}

__global__ void k_deg_count(const int* __restrict__ dst) {
    int e = blockIdx.x * blockDim.x + threadIdx.x;
    if (e < N_EDGES) atomicAdd(&g_deg[dst[e]], 1);
}

__global__ void k_dinv() {
    int i = blockIdx.x * blockDim.x + threadIdx.x;
    if (i < N_NODES) g_dinv[i] = rsqrtf((float)g_deg[i]);
}

__global__ void k_norm(const int* __restrict__ src,
                       const int* __restrict__ dst) {
    int e = blockIdx.x * blockDim.x + threadIdx.x;
    if (e < N_EDGES) g_norm[e] = g_dinv[src[e]] * g_dinv[dst[e]];
}

// ---------------- GEMM: g_lin[N,64] = A[N,K] @ W[K,64] ----------------
// FROM_H=1: read activations from device-global g_h (A arg ignored).
// 256 threads/block, block computes 32 rows x 64 cols; thread holds 8 rows.
template <int K, int FROM_H>
__global__ void k_gemm64(const float* __restrict__ A,
                         const float* __restrict__ W) {
    __shared__ float Ws[64][64];
    __shared__ float As[32][65];

    const float* __restrict__ Asrc = FROM_H ? (const float*)g_h : A;

    const int col = threadIdx.x & 63;
    const int rq  = threadIdx.x >> 6;       // 0..3
    const int row0 = blockIdx.x * 32;

    float acc[8];
#pragma unroll
    for (int r = 0; r < 8; r++) acc[r] = 0.f;

    for (int kc = 0; kc < K; kc += 64) {
        // load W chunk (64x64)
        for (int i = threadIdx.x; i < 64 * 64; i += 256) {
            int kk = i >> 6, cc = i & 63;
            Ws[kk][cc] = W[(size_t)(kc + kk) * 64 + cc];
        }
        // load A chunk (32x64)
        for (int r = rq; r < 32; r += 4) {
            int gr = row0 + r;
            As[r][col] = (gr < N_NODES) ? Asrc[(size_t)gr * K + kc + col] : 0.f;
        }
        __syncthreads();

#pragma unroll
        for (int kk = 0; kk < 64; kk++) {
            float w = Ws[kk][col];
#pragma unroll
            for (int r = 0; r < 8; r++)
                acc[r] = fmaf(As[rq * 8 + r][kk], w, acc[r]);
        }
        __syncthreads();
    }

#pragma unroll
    for (int r = 0; r < 8; r++) {
        int gr = row0 + rq * 8 + r;
        if (gr < N_NODES) g_lin[(size_t)gr * 64 + col] = acc[r];
    }
}

// ---------------- propagation ----------------
// g_agg[i] = dinv[i]^2 * g_lin[i]   (self-loop term; also initializes agg)
__global__ void k_selfloop() {
    int idx = blockIdx.x * blockDim.x + threadIdx.x;
    if (idx < N_NODES * HIDDEN) {
        float d = g_dinv[idx >> 6];
        g_agg[idx] = d * d * g_lin[idx];
    }
}

// g_agg[dst] += norm[e] * g_lin[src], 64 threads per edge
__global__ void k_prop(const int* __restrict__ src,
                       const int* __restrict__ dst) {
    long long t = (long long)blockIdx.x * blockDim.x + threadIdx.x;
    int e = (int)(t >> 6);
    int f = (int)(t & 63);
    if (e < N_EDGES) {
        int s = src[e];
        int d = dst[e];
        float v = g_lin[(size_t)s * 64 + f] * g_norm[e];
        atomicAdd(&g_agg[(size_t)d * 64 + f], v);
    }
}

// h = relu(agg + b); jk = first ? h : max(jk, h)
template <int FIRST>
__global__ void k_epi(const float* __restrict__ b) {
    int idx = blockIdx.x * blockDim.x + threadIdx.x;
    if (idx < N_NODES * HIDDEN) {
        float v = g_agg[idx] + b[idx & 63];
        v = fmaxf(v, 0.f);
        g_h[idx] = v;
        g_jk[idx] = FIRST ? v : fmaxf(g_jk[idx], v);
    }
}

// ---------------- final: logits = jk @ fcW + fcb; log_softmax ----------------
// 256 threads = 4 nodes x 64 threads
__global__ void k_final(const float* __restrict__ fcW,
                        const float* __restrict__ fcb,
                        float* __restrict__ out) {
    __shared__ float Wf[HIDDEN * N_CLASSES];   // 64*40
    __shared__ float row[4][HIDDEN];
    __shared__ float logits[4][N_CLASSES];
    __shared__ float lse[4];

    for (int i = threadIdx.x; i < HIDDEN * N_CLASSES; i += 256)
        Wf[i] = fcW[i];

    const int g = threadIdx.x >> 6;      // node within block (0..3)
    const int f = threadIdx.x & 63;
    const int node = blockIdx.x * 4 + g;

    if (node < N_NODES)
        row[g][f] = g_jk[(size_t)node * HIDDEN + f];
    __syncthreads();

    if (node < N_NODES && f < N_CLASSES) {
        float acc = fcb[f];
#pragma unroll
        for (int h = 0; h < HIDDEN; h++)
            acc = fmaf(row[g][h], Wf[h * N_CLASSES + f], acc);
        logits[g][f] = acc;
    }
    __syncthreads();

    if (node < N_NODES && f == 0) {
        float m = -INFINITY;
#pragma unroll
        for (int c = 0; c < N_CLASSES; c++) m = fmaxf(m, logits[g][c]);
        float s = 0.f;
#pragma unroll
        for (int c = 0; c < N_CLASSES; c++) s += expf(logits[g][c] - m);
        lse[g] = m + logf(s);
    }
    __syncthreads();

    if (node < N_NODES && f < N_CLASSES)
        out[(size_t)node * N_CLASSES + f] = logits[g][f] - lse[g];
}

// ---------------- launch ----------------
extern "C" void kernel_launch(void* const* d_in, const int* in_sizes, int n_in,
                              void* d_out, int out_size) {
    const float* x      = (const float*)d_in[0];
    const int*   edge   = (const int*)d_in[1];     // int64 lowered to int32
    const float* W0     = (const float*)d_in[2];
    const float* b0     = (const float*)d_in[3];
    const float* W_rest = (const float*)d_in[4];
    const float* b_rest = (const float*)d_in[5];
    const float* fcW    = (const float*)d_in[6];
    const float* fcb    = (const float*)d_in[7];
    float* out = (float*)d_out;

    const int* src = edge;
    const int* dst = edge + N_EDGES;

    const int EB = (N_EDGES + 255) / 256;              // 6250
    const int NB = (N_NODES + 255) / 256;
    const int NHB = (N_NODES * HIDDEN + 255) / 256;    // 25000
    const int PB = (int)(((long long)N_EDGES * 64 + 255) / 256);   // 400000
    const int GB = (N_NODES + 31) / 32;                // 3125

    // norm precompute
    k_deg_init <<<NB, 256>>>();
    k_deg_count<<<EB, 256>>>(dst);
    k_dinv     <<<NB, 256>>>();
    k_norm     <<<EB, 256>>>(src, dst);

    // layer 0 (K = 512)
    k_gemm64<IN_FEAT, 0><<<GB, 256>>>(x, W0);
    k_selfloop<<<NHB, 256>>>();
    k_prop    <<<PB, 256>>>(src, dst);
    k_epi<1>  <<<NHB, 256>>>(b0);

    // layers 1..5 (K = 64)
    for (int l = 0; l < N_LAYERS - 1; l++) {
        k_gemm64<HIDDEN, 1><<<GB, 256>>>(nullptr, W_rest + (size_t)l * HIDDEN * HIDDEN);
        k_selfloop<<<NHB, 256>>>();
        k_prop    <<<PB, 256>>>(src, dst);
        k_epi<0>  <<<NHB, 256>>>(b_rest + (size_t)l * HIDDEN);
    }

    // final FC + log_softmax
    k_final<<<(N_NODES + 3) / 4, 256>>>(fcW, fcb, out);
}

// round 5
// speedup vs baseline: 3.6069x; 3.6069x over previous
#include <cuda_runtime.h>
#include <cuda_bf16.h>
#include <math.h>

#define N_NODES   100000
#define N_EDGES   1600000
#define IN_FEAT   512
#define HIDDEN    64
#define N_CLASSES 40
#define N_LAYERS  6

#define SCAN_NB   98   // ceil(100000/1024)

// ---------------- device scratch ----------------
__device__ float g_lin[N_NODES * HIDDEN];
__device__ float g_h  [N_NODES * HIDDEN];
__device__ float g_jk [N_NODES * HIDDEN];
__device__ float g_dinv[N_NODES];
__device__ int   g_deg [N_NODES];
__device__ int   g_off [N_NODES + 1];
__device__ int   g_cur [N_NODES];
__device__ int   g_blk [SCAN_NB];
__device__ int   g_blkpref[SCAN_NB];
__device__ int   g_csr_src[N_EDGES];
__device__ float g_csr_w  [N_EDGES];

// packed dual-fp32 FMA (Blackwell f32x2 pipe, 2x fp32 rate)
#define FMA_F32X2(d, a, b, c) \
    asm("fma.rn.f32x2 %0, %1, %2, %3;" : "=l"(d) : "l"(a), "l"(b), "l"(c))

// ---------------- degree / dinv ----------------
__global__ void k_deg_init() {
    int i = blockIdx.x * blockDim.x + threadIdx.x;
    if (i < N_NODES) g_deg[i] = 1;   // self loop
}

__global__ void k_deg_count(const int* __restrict__ dst) {
    int e = blockIdx.x * blockDim.x + threadIdx.x;
    if (e < N_EDGES) atomicAdd(&g_deg[dst[e]], 1);
}

__global__ void k_dinv() {
    int i = blockIdx.x * blockDim.x + threadIdx.x;
    if (i < N_NODES) g_dinv[i] = rsqrtf((float)g_deg[i]);
}

// ---------------- exclusive scan of (deg-1) -> CSR offsets ----------------
__global__ void k_scan1() {
    __shared__ int sh[1024];
    int i = blockIdx.x * 1024 + threadIdx.x;
    int v = (i < N_NODES) ? (g_deg[i] - 1) : 0;
    sh[threadIdx.x] = v;
    __syncthreads();
#pragma unroll
    for (int o = 1; o < 1024; o <<= 1) {
        int t = (threadIdx.x >= o) ? sh[threadIdx.x - o] : 0;
        __syncthreads();
        sh[threadIdx.x] += t;
        __syncthreads();
    }
    if (i < N_NODES) g_off[i] = sh[threadIdx.x] - v;   // exclusive, intra-block
    if (threadIdx.x == 1023) g_blk[blockIdx.x] = sh[1023];
}

__global__ void k_scan2() {
    __shared__ int sh[SCAN_NB];
    if (threadIdx.x < SCAN_NB) sh[threadIdx.x] = g_blk[threadIdx.x];
    __syncthreads();
    if (threadIdx.x == 0) {
        int run = 0;
        for (int b = 0; b < SCAN_NB; b++) { int t = sh[b]; sh[b] = run; run += t; }
        g_off[N_NODES] = N_EDGES;
    }
    __syncthreads();
    if (threadIdx.x < SCAN_NB) g_blkpref[threadIdx.x] = sh[threadIdx.x];
}

__global__ void k_scan3() {
    int i = blockIdx.x * 1024 + threadIdx.x;
    if (i < N_NODES) {
        int o = g_off[i] + g_blkpref[blockIdx.x];
        g_off[i] = o;
        g_cur[i] = o;
    }
}

// fill CSR buckets (order within bucket irrelevant for a sum)
__global__ void k_fill(const int* __restrict__ src, const int* __restrict__ dst) {
    int e = blockIdx.x * blockDim.x + threadIdx.x;
    if (e < N_EDGES) {
        int s = src[e], d = dst[e];
        int p = atomicAdd(&g_cur[d], 1);
        g_csr_src[p] = s;
        g_csr_w[p]   = g_dinv[s] * g_dinv[d];
    }
}

// ---------------- GEMM: g_lin[N,64] = A[N,K] @ W[K,64] ----------------
// 64x64 block tile, 256 threads, each thread 4 rows x 4 cols via f32x2.
template <int K, int FROM_H>
__global__ void k_gemm64(const float* __restrict__ A,
                         const float* __restrict__ W) {
    __shared__ float As[64][68];   // pad 68 keeps float4 stores 16B-aligned
    __shared__ float Ws[64][64];

    const float* __restrict__ Asrc = FROM_H ? (const float*)g_h : A;

    const int tx = threadIdx.x & 15;     // col group (4 cols)
    const int ty = threadIdx.x >> 4;     // row group (4 rows)
    const int row0 = blockIdx.x * 64;

    unsigned long long acc[4][2];
#pragma unroll
    for (int r = 0; r < 4; r++) { acc[r][0] = 0ull; acc[r][1] = 0ull; }

    for (int kc = 0; kc < K; kc += 64) {
#pragma unroll
        for (int i = 0; i < 4; i++) {          // A chunk: 64x64 = 1024 float4
            int idx = threadIdx.x + i * 256;
            int r = idx >> 4, c4 = idx & 15;
            int gr = row0 + r;
            float4 v = make_float4(0.f, 0.f, 0.f, 0.f);
            if (gr < N_NODES)
                v = *(const float4*)&Asrc[(size_t)gr * K + kc + c4 * 4];
            *(float4*)&As[r][c4 * 4] = v;
        }
#pragma unroll
        for (int i = 0; i < 4; i++) {          // W chunk: 64x64
            int idx = threadIdx.x + i * 256;
            int r = idx >> 4, c4 = idx & 15;
            *(float4*)&Ws[r][c4 * 4] =
                *(const float4*)&W[(size_t)(kc + r) * 64 + c4 * 4];
        }
        __syncthreads();

#pragma unroll 16
        for (int kk = 0; kk < 64; kk++) {
            unsigned long long b0 = *(const unsigned long long*)&Ws[kk][tx * 4];
            unsigned long long b1 = *(const unsigned long long*)&Ws[kk][tx * 4 + 2];
#pragma unroll
            for (int r = 0; r < 4; r++) {
                unsigned int au = __float_as_uint(As[ty * 4 + r][kk]);
                unsigned long long av;
                asm("mov.b64 %0, {%1, %1};" : "=l"(av) : "r"(au));
                FMA_F32X2(acc[r][0], av, b0, acc[r][0]);
                FMA_F32X2(acc[r][1], av, b1, acc[r][1]);
            }
        }
        __syncthreads();
    }

#pragma unroll
    for (int r = 0; r < 4; r++) {
        int gr = row0 + ty * 4 + r;
        if (gr < N_NODES) {
            unsigned int lo0, hi0, lo1, hi1;
            asm("mov.b64 {%0, %1}, %2;" : "=r"(lo0), "=r"(hi0) : "l"(acc[r][0]));
            asm("mov.b64 {%0, %1}, %2;" : "=r"(lo1), "=r"(hi1) : "l"(acc[r][1]));
            float4 o = make_float4(__uint_as_float(lo0), __uint_as_float(hi0),
                                   __uint_as_float(lo1), __uint_as_float(hi1));
            *(float4*)&g_lin[(size_t)gr * 64 + tx * 4] = o;
        }
    }
}

// ---------------- fused aggregation: selfloop + CSR gather + bias/relu/jk ----
// one warp per node, float2 per lane (64 features)
template <int FIRST>
__global__ void k_gather(const float* __restrict__ b) {
    int gw   = (blockIdx.x * blockDim.x + threadIdx.x) >> 5;
    int lane = threadIdx.x & 31;
    if (gw >= N_NODES) return;

    const float2* __restrict__ lin2 = (const float2*)g_lin;
    float dn = g_dinv[gw];
    float2 self = lin2[(size_t)gw * 32 + lane];
    float2 acc = make_float2(dn * dn * self.x, dn * dn * self.y);

    int j = g_off[gw], end = g_off[gw + 1];
    for (; j + 4 <= end; j += 4) {
        int   s0 = g_csr_src[j],   s1 = g_csr_src[j + 1];
        int   s2 = g_csr_src[j + 2], s3 = g_csr_src[j + 3];
        float w0 = g_csr_w[j],     w1 = g_csr_w[j + 1];
        float w2 = g_csr_w[j + 2], w3 = g_csr_w[j + 3];
        float2 m0 = lin2[(size_t)s0 * 32 + lane];
        float2 m1 = lin2[(size_t)s1 * 32 + lane];
        float2 m2 = lin2[(size_t)s2 * 32 + lane];
        float2 m3 = lin2[(size_t)s3 * 32 + lane];
        acc.x = fmaf(w0, m0.x, fmaf(w1, m1.x, fmaf(w2, m2.x, fmaf(w3, m3.x, acc.x))));
        acc.y = fmaf(w0, m0.y, fmaf(w1, m1.y, fmaf(w2, m2.y, fmaf(w3, m3.y, acc.y))));
    }
    for (; j < end; j++) {
        int s = g_csr_src[j];
        float w = g_csr_w[j];
        float2 m = lin2[(size_t)s * 32 + lane];
        acc.x = fmaf(w, m.x, acc.x);
        acc.y = fmaf(w, m.y, acc.y);
    }

    float vx = fmaxf(acc.x + b[lane * 2],     0.f);
    float vy = fmaxf(acc.y + b[lane * 2 + 1], 0.f);
    ((float2*)g_h)[(size_t)gw * 32 + lane] = make_float2(vx, vy);
    float2* jk2 = (float2*)g_jk;
    if (FIRST) {
        jk2[(size_t)gw * 32 + lane] = make_float2(vx, vy);
    } else {
        float2 o = jk2[(size_t)gw * 32 + lane];
        jk2[(size_t)gw * 32 + lane] = make_float2(fmaxf(o.x, vx), fmaxf(o.y, vy));
    }
}

// ---------------- final: logits = jk @ fcW + fcb; log_softmax ----------------
__global__ void k_final(const float* __restrict__ fcW,
                        const float* __restrict__ fcb,
                        float* __restrict__ out) {
    __shared__ float Wf[HIDDEN * N_CLASSES];
    __shared__ float row[4][HIDDEN];
    __shared__ float logits[4][N_CLASSES];
    __shared__ float lse[4];

    for (int i = threadIdx.x; i < HIDDEN * N_CLASSES; i += 256)
        Wf[i] = fcW[i];

    const int g = threadIdx.x >> 6;
    const int f = threadIdx.x & 63;
    const int node = blockIdx.x * 4 + g;

    if (node < N_NODES)
        row[g][f] = g_jk[(size_t)node * HIDDEN + f];
    __syncthreads();

    if (node < N_NODES && f < N_CLASSES) {
        float acc = fcb[f];
#pragma unroll
        for (int h = 0; h < HIDDEN; h++)
            acc = fmaf(row[g][h], Wf[h * N_CLASSES + f], acc);
        logits[g][f] = acc;
    }
    __syncthreads();

    if (node < N_NODES && f == 0) {
        float m = -INFINITY;
#pragma unroll
        for (int c = 0; c < N_CLASSES; c++) m = fmaxf(m, logits[g][c]);
        float s = 0.f;
#pragma unroll
        for (int c = 0; c < N_CLASSES; c++) s += expf(logits[g][c] - m);
        lse[g] = m + logf(s);
    }
    __syncthreads();

    if (node < N_NODES && f < N_CLASSES)
        out[(size_t)node * N_CLASSES + f] = logits[g][f] - lse[g];
}

// ---------------- launch ----------------
extern "C" void kernel_launch(void* const* d_in, const int* in_sizes, int n_in,
                              void* d_out, int out_size) {
    const float* x      = (const float*)d_in[0];
    const int*   edge   = (const int*)d_in[1];     // int64 lowered to int32
    const float* W0     = (const float*)d_in[2];
    const float* b0     = (const float*)d_in[3];
    const float* W_rest = (const float*)d_in[4];
    const float* b_rest = (const float*)d_in[5];
    const float* fcW    = (const float*)d_in[6];
    const float* fcb    = (const float*)d_in[7];
    float* out = (float*)d_out;

    const int* src = edge;
    const int* dst = edge + N_EDGES;

    const int EB = (N_EDGES + 255) / 256;          // 6250
    const int NB = (N_NODES + 255) / 256;
    const int GB = (N_NODES + 63) / 64;            // 1563
    const int AB = (N_NODES * 32 + 255) / 256;     // 12500 (warp per node)

    // graph precompute -> CSR
    k_deg_init <<<NB, 256>>>();
    k_deg_count<<<EB, 256>>>(dst);
    k_dinv     <<<NB, 256>>>();
    k_scan1    <<<SCAN_NB, 1024>>>();
    k_scan2    <<<1, 128>>>();
    k_scan3    <<<SCAN_NB, 1024>>>();
    k_fill     <<<EB, 256>>>(src, dst);

    // layer 0 (K = 512)
    k_gemm64<IN_FEAT, 0><<<GB, 256>>>(x, W0);
    k_gather<1><<<AB, 256>>>(b0);

    // layers 1..5 (K = 64)
    for (int l = 0; l < N_LAYERS - 1; l++) {
        k_gemm64<HIDDEN, 1><<<GB, 256>>>(nullptr, W_rest + (size_t)l * HIDDEN * HIDDEN);
        k_gather<0><<<AB, 256>>>(b_rest + (size_t)l * HIDDEN);
    }

    // final FC + log_softmax
    k_final<<<(N_NODES + 3) / 4, 256>>>(fcW, fcb, out);
}